// round 8
// baseline (speedup 1.0000x reference)
#include <cuda_runtime.h>
#include <cuda_fp16.h>
#include <cstdint>

#define NB 16
#define NC 64          // C_IN == C_OUT == 64
#define VIN 40962
#define VOUT 163842
#define VT 128         // stage-2 vertices per block

// Scratch: y[b][u][o] in fp16, rows of 128B. 84 MB (mostly L2-resident).
__device__ __half g_y[(size_t)NB * VIN * NC];
// 1 if idx buffer is int64, 0 if int32.
__device__ int g_idx_is64;

static __device__ __forceinline__ uint32_t pack_h2(float a, float b) {
    __half2 h = __floats2half2_rn(a, b);
    return *(uint32_t*)&h;
}

static __device__ __forceinline__ void mma16816(float* d, const uint32_t* a,
                                                uint32_t b0, uint32_t b1) {
    asm volatile(
        "mma.sync.aligned.m16n8k16.row.col.f32.f16.f16.f32 "
        "{%0,%1,%2,%3}, {%4,%5,%6,%7}, {%8,%9}, {%0,%1,%2,%3};"
        : "+f"(d[0]), "+f"(d[1]), "+f"(d[2]), "+f"(d[3])
        : "r"(a[0]), "r"(a[1]), "r"(a[2]), "r"(a[3]), "r"(b0), "r"(b1));
}

// ---------------------------------------------------------------------------
// Stage 1 (unchanged): y = x^T W^T via m16n8k16 HMMA, f32 accum, fp16 store.
// ---------------------------------------------------------------------------
__global__ __launch_bounds__(128)
void stage1_mma(const float* __restrict__ x, const float* __restrict__ W,
                const void* __restrict__ idx_raw) {
    __shared__ uint32_t xs[128][33];
    __shared__ uint32_t wb[64][33];

    const int b   = blockIdx.y;
    const int u0  = blockIdx.x * 128;
    const int tid = threadIdx.x;

    if (b == 0 && blockIdx.x == 0 && tid == 0) {
        const int* p = (const int*)idx_raw;
        int all_odd_zero = 1;
#pragma unroll
        for (int k = 0; k < 8; k++)
            if (p[2 * k + 1] != 0) all_odd_zero = 0;
        g_idx_is64 = all_odd_zero;
    }

    for (int i = tid; i < 64 * 32; i += 128) {
        int o = i >> 5, cp = i & 31;
        float2 wv = *(const float2*)&W[o * 64 + cp * 2];
        wb[o][cp] = pack_h2(wv.x, wv.y);
    }

    const float* xb = x + (size_t)b * NC * VIN + u0;
    if (u0 + 128 <= VIN) {
#pragma unroll
        for (int i = tid; i < 32 * 64; i += 128) {
            int cp = i >> 6, up = i & 63;
            const float* p0 = xb + (size_t)(2 * cp) * VIN;
            float2 v0 = __ldcs((const float2*)(p0 + 2 * up));
            float2 v1 = __ldcs((const float2*)(p0 + VIN + 2 * up));
            xs[2 * up][cp]     = pack_h2(v0.x, v1.x);
            xs[2 * up + 1][cp] = pack_h2(v0.y, v1.y);
        }
    } else {
        for (int i = tid; i < 32 * 64; i += 128) {
            int cp = i >> 6, up = i & 63;
            const float* p0 = xb + (size_t)(2 * cp) * VIN;
            int uA = 2 * up, uB = 2 * up + 1;
            float a0 = (u0 + uA < VIN) ? p0[uA] : 0.0f;
            float a1 = (u0 + uA < VIN) ? p0[VIN + uA] : 0.0f;
            float b0 = (u0 + uB < VIN) ? p0[uB] : 0.0f;
            float b1 = (u0 + uB < VIN) ? p0[VIN + uB] : 0.0f;
            xs[uA][cp] = pack_h2(a0, a1);
            xs[uB][cp] = pack_h2(b0, b1);
        }
    }
    __syncthreads();

    const int lane = tid & 31, wid = tid >> 5;
    const int g = lane >> 2, t = lane & 3;
    const int ub = wid * 32;

    float acc[2][8][4];
#pragma unroll
    for (int mt = 0; mt < 2; mt++)
#pragma unroll
        for (int nt = 0; nt < 8; nt++)
#pragma unroll
            for (int r = 0; r < 4; r++) acc[mt][nt][r] = 0.0f;

#pragma unroll
    for (int kt = 0; kt < 4; kt++) {
        uint32_t a[2][4];
#pragma unroll
        for (int mt = 0; mt < 2; mt++) {
            int r = ub + mt * 16;
            a[mt][0] = xs[r + g][kt * 8 + t];
            a[mt][1] = xs[r + 8 + g][kt * 8 + t];
            a[mt][2] = xs[r + g][kt * 8 + 4 + t];
            a[mt][3] = xs[r + 8 + g][kt * 8 + 4 + t];
        }
#pragma unroll
        for (int nt = 0; nt < 8; nt++) {
            uint32_t b0 = wb[nt * 8 + g][kt * 8 + t];
            uint32_t b1 = wb[nt * 8 + g][kt * 8 + 4 + t];
            mma16816(acc[0][nt], a[0], b0, b1);
            mma16816(acc[1][nt], a[1], b0, b1);
        }
    }

    __syncthreads();
    uint32_t* ys = (uint32_t*)xs;
#pragma unroll
    for (int mt = 0; mt < 2; mt++) {
        int r0 = ub + mt * 16 + g;
#pragma unroll
        for (int nt = 0; nt < 8; nt++) {
            ys[r0 * 33 + nt * 4 + t]       = pack_h2(acc[mt][nt][0], acc[mt][nt][1]);
            ys[(r0 + 8) * 33 + nt * 4 + t] = pack_h2(acc[mt][nt][2], acc[mt][nt][3]);
        }
    }
    __syncthreads();

    __half* yb = g_y + (size_t)b * VIN * NC;
#pragma unroll
    for (int i = tid; i < 128 * 8; i += 128) {
        int u = i >> 3, q = i & 7;
        if (u0 + u < VIN) {
            const uint32_t* row = ys + u * 33 + q * 4;
            uint4 v = make_uint4(row[0], row[1], row[2], row[3]);
            *(uint4*)&yb[(size_t)(u0 + u) * NC + q * 8] = v;
        }
    }
}

// ---------------------------------------------------------------------------
// Stage 2 v3: out[b,o,v] = 0.5*(y[i0]+y[i1]) + bias[o]
// 128-vertex tiles. Indices staged in smem (coalesced). Gather keeps 4
// LDG.128 in flight per warp step. fp16 t with stride 66 (all smem phases
// bank-conflict-free). Write: LDS.16 + FADD + coalesced STG.32.
// ---------------------------------------------------------------------------
__global__ __launch_bounds__(256)
void stage2_gather(const void* __restrict__ idx_raw,
                   const float* __restrict__ bias,
                   float* __restrict__ out) {
    __shared__ __half t[VT][66];     // 16.9 KB, stride 66 halves (132B)
    __shared__ int    idx_s[VT][2];  // 1 KB
    __shared__ float  bs[64];

    const int b    = blockIdx.y;
    const int v0   = blockIdx.x * VT;
    const int tid  = threadIdx.x;
    const int lane = tid & 31;
    const int w    = tid >> 5;
    const int is64 = g_idx_is64;

    // ---- stage indices into smem (coalesced; clamp; both dtypes) ----
    {
        const int vl = tid >> 1, sl = tid & 1;   // 256 threads = 128 x 2 slots
        const int v  = v0 + vl;
        long long id = 0;
        if (v < VOUT) {
            if (is64) id = ((const long long*)idx_raw)[(size_t)v * 2 + sl];
            else      id = ((const int*)idx_raw)[(size_t)v * 2 + sl];
        }
        id = id < 0 ? 0 : (id >= VIN ? VIN - 1 : id);
        idx_s[vl][sl] = (int)id;
    }
    if (tid < 64) bs[tid] = bias[tid];
    __syncthreads();

    const __half* yb = g_y + (size_t)b * VIN * NC;

    // ---- gather: warp w owns vertices [w*16, w*16+16) ----
    const int g = lane >> 3;      // vertex within quad (4 per warp-instr)
    const int s = lane & 7;       // 16B chunk within 128B y-row
#pragma unroll
    for (int ii = 0; ii < 2; ii++) {
        uint4 A[2], B[2];
        int vl[2];
#pragma unroll
        for (int p = 0; p < 2; p++) {            // 4 LDG.128 issued back-to-back
            vl[p] = w * 16 + ii * 8 + p * 4 + g;
            int i0 = idx_s[vl[p]][0];
            int i1 = idx_s[vl[p]][1];
            A[p] = *(const uint4*)(yb + (size_t)i0 * NC + s * 8);
            B[p] = *(const uint4*)(yb + (size_t)i1 * NC + s * 8);
        }
#pragma unroll
        for (int p = 0; p < 2; p++) {
            union { uint4 u; __half2 h[4]; } a, d;
            a.u = A[p]; d.u = B[p];
            uint32_t* trow = (uint32_t*)&t[vl[p]][s * 8];   // s*8 even -> 4B aligned
#pragma unroll
            for (int k = 0; k < 4; k++) {
                float2 fa = __half22float2(a.h[k]);
                float2 fb = __half22float2(d.h[k]);
                trow[k] = pack_h2(0.5f * (fa.x + fb.x), 0.5f * (fa.y + fb.y));
            }
        }
    }
    __syncthreads();

    // ---- write: warp w -> o in [w*8, w*8+8); 32 consecutive v per STG ----
    {
        float* ob = out + (size_t)b * NC * VOUT + v0;
#pragma unroll
        for (int j = 0; j < 8; j++) {
            const int o  = w * 8 + j;
            const float bo = bs[o];
            float* orow = ob + (size_t)o * VOUT;
#pragma unroll
            for (int vq = 0; vq < 4; vq++) {
                const int v = vq * 32 + lane;
                if (v0 + v < VOUT)
                    __stcs(orow + v, __half2float(t[v][o]) + bo);
            }
        }
    }
}

// ---------------------------------------------------------------------------
extern "C" void kernel_launch(void* const* d_in, const int* in_sizes, int n_in,
                              void* d_out, int out_size) {
    const float* x = nullptr;
    const void*  idx = nullptr;
    const float* W = nullptr;
    const float* bias = nullptr;
    for (int i = 0; i < n_in; i++) {
        switch (in_sizes[i]) {
            case 41945088: x    = (const float*)d_in[i]; break;  // 16*64*40962
            case 327684:   idx  = d_in[i];               break;  // 163842*2
            case 4096:     W    = (const float*)d_in[i]; break;  // 64*64
            case 64:       bias = (const float*)d_in[i]; break;  // 64
            default: break;
        }
    }
    float* out = (float*)d_out;
    (void)out_size;

    dim3 g1((VIN + 127) / 128, NB);
    stage1_mma<<<g1, 128>>>(x, W, idx);

    dim3 g2((VOUT + VT - 1) / VT, NB);
    stage2_gather<<<g2, 256>>>(idx, bias, out);
}